// round 1
// baseline (speedup 1.0000x reference)
#include <cuda_runtime.h>

// ---------------------------------------------------------------------------
// MultiHeadAttention: B=2, S=2048, E=1024, H=16, D=64, fp32.
// Pipeline:
//   1) 3x projection GEMM  C[4096,1024] = X @ W^T + b, scattered to [B,H,S,D]
//   2) flash attention per (b,h): Q[2048,64] x K x V with online softmax
//   3) output GEMM to d_out [4096,1024]
// All heavy loops use packed fma.rn.f32x2 (2 MACs/instr; 3-reg FFMA is
// half-rate on sm_103a).
// ---------------------------------------------------------------------------

typedef unsigned long long ull;

#define DI __device__ __forceinline__

DI ull pk2(float lo, float hi) {
    ull r; asm("mov.b64 %0, {%1,%2};" : "=l"(r) : "f"(lo), "f"(hi)); return r;
}
DI void upk2(ull v, float& lo, float& hi) {
    asm("mov.b64 {%0,%1}, %2;" : "=f"(lo), "=f"(hi) : "l"(v));
}
DI ull ffma2(ull a, ull b, ull c) {
    ull d; asm("fma.rn.f32x2 %0, %1, %2, %3;" : "=l"(d) : "l"(a), "l"(b), "l"(c)); return d;
}
DI ull fmul2(ull a, ull b) {
    ull d; asm("mul.rn.f32x2 %0, %1, %2;" : "=l"(d) : "l"(a), "l"(b)); return d;
}

constexpr int B = 2, S = 2048, E = 1024, H = 16, D = 64;

// Scratch (allocation-free rule: static __device__ globals)
__device__ float g_q[B * H * S * D];
__device__ float g_k[B * H * S * D];
__device__ float g_v[B * H * S * D];
__device__ float g_att[B * S * E];

// ---------------------------------------------------------------------------
// GEMM: C[m,n] = sum_k X[m,k] * W[n,k] + bias[n]
//   MODE 0: scatter rows m=(b,s), cols n=(h,d) into [B,H,S,D] buffer
//   MODE 1: plain row-major [M,N] output
// 128x128 tile, BK=8, 256 threads, 8x8 per thread, f32x2 packed inner loop.
// ---------------------------------------------------------------------------
template <int MODE>
__global__ __launch_bounds__(256) void gemm_kernel(const float* __restrict__ X,
                                                   const float* __restrict__ W,
                                                   const float* __restrict__ bias,
                                                   float* __restrict__ out)
{
    __shared__ float As[8][132];
    __shared__ float Ws[8][132];

    const int tid = threadIdx.x;
    const int tx = tid & 15, ty = tid >> 4;
    const int m0 = blockIdx.y * 128;
    const int n0 = blockIdx.x * 128;
    const int lr = tid >> 1;        // 0..127 (load row)
    const int lc = (tid & 1) << 2;  // 0 or 4 (load k-offset)

    const float* Xp = X + (m0 + lr) * 1024 + lc;
    const float* Wp = W + (n0 + lr) * 1024 + lc;

    ull acc[8][4];
#pragma unroll
    for (int i = 0; i < 8; i++)
#pragma unroll
        for (int j = 0; j < 4; j++) acc[i][j] = 0ull;

    float4 av = *(const float4*)Xp;
    float4 wv = *(const float4*)Wp;

    for (int k0 = 0; k0 < 1024; k0 += 8) {
        __syncthreads();
        As[lc + 0][lr] = av.x; As[lc + 1][lr] = av.y;
        As[lc + 2][lr] = av.z; As[lc + 3][lr] = av.w;
        Ws[lc + 0][lr] = wv.x; Ws[lc + 1][lr] = wv.y;
        Ws[lc + 2][lr] = wv.z; Ws[lc + 3][lr] = wv.w;
        __syncthreads();
        if (k0 + 8 < 1024) {
            av = *(const float4*)(Xp + k0 + 8);
            wv = *(const float4*)(Wp + k0 + 8);
        }
#pragma unroll
        for (int kk = 0; kk < 8; kk++) {
            float4 a0 = *(const float4*)&As[kk][ty * 4];
            float4 a1 = *(const float4*)&As[kk][64 + ty * 4];
            ulonglong2 b0 = *(const ulonglong2*)&Ws[kk][tx * 4];
            ulonglong2 b1 = *(const ulonglong2*)&Ws[kk][64 + tx * 4];
            float a[8] = {a0.x, a0.y, a0.z, a0.w, a1.x, a1.y, a1.z, a1.w};
            ull bv[4] = {b0.x, b0.y, b1.x, b1.y};
#pragma unroll
            for (int i = 0; i < 8; i++) {
                ull a2 = pk2(a[i], a[i]);
#pragma unroll
                for (int j = 0; j < 4; j++) acc[i][j] = ffma2(a2, bv[j], acc[i][j]);
            }
        }
    }

    float4 bias0 = *(const float4*)&bias[n0 + tx * 4];
    float4 bias1 = *(const float4*)&bias[n0 + 64 + tx * 4];

#pragma unroll
    for (int i = 0; i < 8; i++) {
        int m = m0 + (i >> 2) * 64 + ty * 4 + (i & 3);
        float4 r0, r1;
        upk2(acc[i][0], r0.x, r0.y); upk2(acc[i][1], r0.z, r0.w);
        upk2(acc[i][2], r1.x, r1.y); upk2(acc[i][3], r1.z, r1.w);
        r0.x += bias0.x; r0.y += bias0.y; r0.z += bias0.z; r0.w += bias0.w;
        r1.x += bias1.x; r1.y += bias1.y; r1.z += bias1.z; r1.w += bias1.w;
        if (MODE == 0) {
            int bb = m >> 11, ss = m & 2047;
            int nA = n0 + tx * 4;
            int nB = n0 + 64 + tx * 4;
            int hA = nA >> 6, dA = nA & 63;
            int hB = nB >> 6, dB = nB & 63;
            *(float4*)&out[((bb * H + hA) * S + ss) * D + dA] = r0;
            *(float4*)&out[((bb * H + hB) * S + ss) * D + dB] = r1;
        } else {
            *(float4*)&out[m * 1024 + n0 + tx * 4] = r0;
            *(float4*)&out[m * 1024 + n0 + 64 + tx * 4] = r1;
        }
    }
}

// ---------------------------------------------------------------------------
// Flash attention. One thread owns one Q row (BQ=128 rows / 128 threads).
// Q tile in smem [r][68] (pre-scaled by 1/8). K tile stored d-major
// transposed [d][68] so key-pairs are contiguous (f32x2 over keys, K reads
// are warp-broadcast). V tile row-major [j][64] (f32x2 over d, broadcast).
// ---------------------------------------------------------------------------
constexpr int BQ = 128;
constexpr int TK = 64;
constexpr int QPAD = 68;
constexpr int ATTN_SMEM = (BQ * QPAD + TK * QPAD + TK * D) * 4;  // 68,608 B

__global__ __launch_bounds__(128) void attn_kernel(const float* __restrict__ Q,
                                                   const float* __restrict__ K,
                                                   const float* __restrict__ V,
                                                   float* __restrict__ Oout)
{
    extern __shared__ float sm[];
    float* Qs  = sm;                    // [BQ][QPAD]
    float* Kst = sm + BQ * QPAD;        // [D][QPAD] (d-major)
    float* Vs  = Kst + TK * QPAD;       // [TK][D]

    const int t  = threadIdx.x;
    const int bh = blockIdx.y;
    const int q0 = blockIdx.x * BQ;
    const float* Qb = Q + bh * (S * D);
    const float* Kb = K + bh * (S * D);
    const float* Vb = V + bh * (S * D);

    // load Q tile (scaled by 1/sqrt(64))
#pragma unroll
    for (int i = 0; i < BQ * D / 128; i++) {
        int idx = i * 128 + t;
        int r = idx >> 6, d = idx & 63;
        Qs[r * QPAD + d] = Qb[(q0 + r) * D + d] * 0.125f;
    }

    ull s2[32], o2[32];
    float m_run = -3.0e38f, l_run = 0.0f;
#pragma unroll
    for (int i = 0; i < 32; i++) o2[i] = 0ull;

    const int r = t;

    for (int kt = 0; kt < S; kt += TK) {
        __syncthreads();  // previous tile fully consumed (also orders Q load on 1st iter)
#pragma unroll
        for (int i = 0; i < TK * D / 128; i++) {
            int idx = i * 128 + t;
            int j = idx >> 6, d = idx & 63;
            float kvl = Kb[(kt + j) * D + d];
            float vvl = Vb[(kt + j) * D + d];
            Kst[d * QPAD + j] = kvl;  // transposed
            Vs[j * D + d] = vvl;
        }
        __syncthreads();

        // scores: s2[i] holds keys (2i, 2i+1)
#pragma unroll
        for (int i = 0; i < 32; i++) s2[i] = 0ull;
        for (int dc = 0; dc < D; dc += 16) {
            float4 qv[4];
#pragma unroll
            for (int i = 0; i < 4; i++)
                qv[i] = *(const float4*)&Qs[r * QPAD + dc + i * 4];
            const float* qf = (const float*)qv;
#pragma unroll
            for (int dd = 0; dd < 16; dd++) {
                ull q2 = pk2(qf[dd], qf[dd]);
                const ulonglong2* kr = (const ulonglong2*)&Kst[(dc + dd) * QPAD];
#pragma unroll
                for (int jp = 0; jp < 16; jp++) {
                    ulonglong2 kv = kr[jp];
                    s2[2 * jp]     = ffma2(q2, kv.x, s2[2 * jp]);
                    s2[2 * jp + 1] = ffma2(q2, kv.y, s2[2 * jp + 1]);
                }
            }
        }

        // online softmax
        float mnew = m_run;
#pragma unroll
        for (int i = 0; i < 32; i++) {
            float a, b2; upk2(s2[i], a, b2);
            mnew = fmaxf(mnew, fmaxf(a, b2));
        }
        float alpha = __expf(m_run - mnew);
        l_run *= alpha;
        float lsum = 0.0f;
#pragma unroll
        for (int i = 0; i < 32; i++) {
            float a, b2; upk2(s2[i], a, b2);
            float p0 = __expf(a - mnew);
            float p1 = __expf(b2 - mnew);
            lsum += p0 + p1;
            s2[i] = pk2(p0, p1);
        }
        l_run += lsum;
        ull al2 = pk2(alpha, alpha);
#pragma unroll
        for (int i = 0; i < 32; i++) o2[i] = fmul2(o2[i], al2);
        m_run = mnew;

        // O update: o2[c] pairs over head-dim; V reads broadcast
        for (int j2 = 0; j2 < 32; j2++) {
            float p0, p1; upk2(s2[j2], p0, p1);
            ull pa = pk2(p0, p0), pb = pk2(p1, p1);
            const ulonglong2* v0 = (const ulonglong2*)&Vs[(2 * j2) * D];
            const ulonglong2* v1 = (const ulonglong2*)&Vs[(2 * j2 + 1) * D];
#pragma unroll
            for (int cp = 0; cp < 16; cp++) {
                ulonglong2 va = v0[cp];
                ulonglong2 vb = v1[cp];
                o2[2 * cp]     = ffma2(pa, va.x, o2[2 * cp]);
                o2[2 * cp + 1] = ffma2(pa, va.y, o2[2 * cp + 1]);
                o2[2 * cp]     = ffma2(pb, vb.x, o2[2 * cp]);
                o2[2 * cp + 1] = ffma2(pb, vb.y, o2[2 * cp + 1]);
            }
        }
    }

    // epilogue: normalize, write merged [B,S,E] layout
    float inv_l = 1.0f / l_run;
    int bb = bh >> 4, hh = bh & 15;
    float* dst = Oout + (bb * S + q0 + r) * E + hh * D;
#pragma unroll
    for (int cp = 0; cp < 16; cp++) {
        float x0, x1, x2, x3;
        upk2(o2[2 * cp], x0, x1);
        upk2(o2[2 * cp + 1], x2, x3);
        float4 o4 = {x0 * inv_l, x1 * inv_l, x2 * inv_l, x3 * inv_l};
        *(float4*)&dst[cp * 4] = o4;
    }
}

// ---------------------------------------------------------------------------
extern "C" void kernel_launch(void* const* d_in, const int* in_sizes, int n_in,
                              void* d_out, int out_size)
{
    const float* query = (const float*)d_in[0];
    const float* key   = (const float*)d_in[1];
    const float* value = (const float*)d_in[2];
    const float* Wq    = (const float*)d_in[3];
    const float* bq    = (const float*)d_in[4];
    const float* Wk    = (const float*)d_in[5];
    const float* bk    = (const float*)d_in[6];
    const float* Wv    = (const float*)d_in[7];
    const float* bv    = (const float*)d_in[8];
    const float* Wo    = (const float*)d_in[9];
    const float* bo    = (const float*)d_in[10];

    void *pq, *pk, *pv, *patt;
    cudaGetSymbolAddress(&pq, g_q);
    cudaGetSymbolAddress(&pk, g_k);
    cudaGetSymbolAddress(&pv, g_v);
    cudaGetSymbolAddress(&patt, g_att);

    cudaFuncSetAttribute(attn_kernel, cudaFuncAttributeMaxDynamicSharedMemorySize,
                         ATTN_SMEM);

    dim3 ggrid(E / 128, (B * S) / 128);  // (8, 32)
    gemm_kernel<0><<<ggrid, 256>>>(query, Wq, bq, (float*)pq);
    gemm_kernel<0><<<ggrid, 256>>>(key,   Wk, bk, (float*)pk);
    gemm_kernel<0><<<ggrid, 256>>>(value, Wv, bv, (float*)pv);

    dim3 agrid(S / BQ, B * H);  // (16, 32)
    attn_kernel<<<agrid, 128, ATTN_SMEM>>>((const float*)pq, (const float*)pk,
                                           (const float*)pv, (float*)patt);

    gemm_kernel<1><<<ggrid, 256>>>((const float*)patt, Wo, bo, (float*)d_out);
}